// round 8
// baseline (speedup 1.0000x reference)
#include <cuda_runtime.h>

// Sliding-window attention: B=1, S=2048, H=8, D=64, window +-64 (129 keys), fp32.
// Lane-pair key-stationary scheme: 2 lanes per query (each owns 32 head dims),
// warp = 16 consecutive queries. All lanes broadcast-read the same K/V smem row
// (two 16B addresses per LDS.128, bank-disjoint via +36-float half offset).
// No-max softmax in exp2 domain. Packed f32x2 FMA. 16 warps/SM.

#define S_LEN   2048
#define NH      8
#define HD      64
#define WIN     64
#define TQ      64                      // queries per block
#define NROWS   (TQ + 2*WIN)            // 192 staged key rows
#define RSTRIDE 68                      // padded row stride (floats)
#define HOFF    36                      // float offset of dim-half 1 in a row
#define GWIN    144                     // key window rows per 16-query group
#define KPS     (GWIN/2)                // 72 keys per split-warp
#define SMEM_FLOATS (2*NROWS*RSTRIDE)
#define SMEM_BYTES  (SMEM_FLOATS*4)     // 104448 B

typedef unsigned long long ull;

__device__ __forceinline__ ull ffma2(ull a, ull b, ull c) {
    ull d;
    asm("fma.rn.f32x2 %0, %1, %2, %3;" : "=l"(d) : "l"(a), "l"(b), "l"(c));
    return d;
}
__device__ __forceinline__ ull fadd2(ull a, ull b) {
    ull d;
    asm("add.rn.f32x2 %0, %1, %2;" : "=l"(d) : "l"(a), "l"(b));
    return d;
}
__device__ __forceinline__ ull fmul2(ull a, ull b) {
    ull d;
    asm("mul.rn.f32x2 %0, %1, %2;" : "=l"(d) : "l"(a), "l"(b));
    return d;
}
__device__ __forceinline__ ull pack2(float lo, float hi) {
    ull d;
    asm("mov.b64 %0, {%1, %2};" : "=l"(d) : "f"(lo), "f"(hi));
    return d;
}
__device__ __forceinline__ float2 unpack2(ull a) {
    float lo, hi;
    asm("mov.b64 {%0, %1}, %2;" : "=f"(lo), "=f"(hi) : "l"(a));
    return make_float2(lo, hi);
}

__global__ void __launch_bounds__(256, 2) swa_kernel(
    const float* __restrict__ Q,
    const float* __restrict__ K,
    const float* __restrict__ V,
    float* __restrict__ O)
{
    extern __shared__ float smem[];
    float* Ksh = smem;
    float* Vsh = smem + NROWS * RSTRIDE;

    const int h    = blockIdx.y;
    const int q0   = blockIdx.x * TQ;
    const int tid  = threadIdx.x;
    const int lane = tid & 31;
    const int w    = tid >> 5;        // warp 0..7
    const int g    = w & 3;           // query group of 16
    const int sp   = w >> 2;          // key split 0/1 (72 keys each)
    const int half = lane & 1;        // head-dim half
    const int ql16 = lane >> 1;       // query index within group

    const int base = q0 - WIN;        // key index of smem row 0

    // ---- stage K/V rows [q0-64, q0+127], padded layout, zero-fill OOB ----
    for (int idx = tid; idx < NROWS * 16; idx += 256) {
        const int row = idx >> 4;
        const int c   = idx & 15;
        const int k   = base + row;
        float4 kv = make_float4(0.f, 0.f, 0.f, 0.f);
        float4 vv = make_float4(0.f, 0.f, 0.f, 0.f);
        if ((unsigned)k < S_LEN) {
            const size_t off = (size_t)(k * NH + h) * 16 + c;
            kv = reinterpret_cast<const float4*>(K)[off];
            vv = reinterpret_cast<const float4*>(V)[off];
        }
        const int fo = row * RSTRIDE + c * 4 + ((c >> 3) << 2); // +4 pad at half
        *reinterpret_cast<float4*>(Ksh + fo) = kv;
        *reinterpret_cast<float4*>(Vsh + fo) = vv;
    }

    // ---- load this lane's query half, pre-scaled by log2(e)/8 ----
    const int q = q0 + g * 16 + ql16;
    ull q2[16];
    {
        const ulonglong2* qp = reinterpret_cast<const ulonglong2*>(
            Q + (size_t)(q * NH + h) * HD + half * 32);
        const float sc = 0.125f * 1.44269504088896340736f;
        const ull sc2 = pack2(sc, sc);
        #pragma unroll
        for (int i = 0; i < 8; i++) {
            ulonglong2 t = qp[i];
            q2[2*i+0] = fmul2(t.x, sc2);
            q2[2*i+1] = fmul2(t.y, sc2);
        }
    }

    const int klo = (q >= WIN) ? q - WIN : 0;
    const int khi = (q + WIN <= S_LEN - 1) ? q + WIN : S_LEN - 1;

    __syncthreads();

    float l = 0.f;
    ull acc2[16];
    #pragma unroll
    for (int i = 0; i < 16; i++) acc2[i] = 0ULL;

    // ---- key loop: 72 keys for this (group, split) ----
    const int r0 = g * 16 + sp * KPS;

    #pragma unroll 2
    for (int kk = 0; kk < KPS; ++kk) {
        const int row = r0 + kk;
        const int k   = base + row;
        const ulonglong2* kr = reinterpret_cast<const ulonglong2*>(
            Ksh + row * RSTRIDE + half * HOFF);
        const ulonglong2* vr = reinterpret_cast<const ulonglong2*>(
            Vsh + row * RSTRIDE + half * HOFF);

        ull d[4];
        #pragma unroll
        for (int i = 0; i < 4; i++) d[i] = 0ULL;
        #pragma unroll
        for (int i = 0; i < 8; i++) {
            const ulonglong2 kv = kr[i];          // 2-addr broadcast LDS.128
            d[(2*i)   & 3] = ffma2(q2[2*i],   kv.x, d[(2*i)   & 3]);
            d[(2*i+1) & 3] = ffma2(q2[2*i+1], kv.y, d[(2*i+1) & 3]);
        }
        ull e0 = fadd2(d[0], d[1]);
        ull e1 = fadd2(d[2], d[3]);
        float2 sv = unpack2(fadd2(e0, e1));
        const float part = sv.x + sv.y;           // this half's partial dot
        const float s = part + __shfl_xor_sync(0xffffffffu, part, 1);

        float p = exp2f(s);                        // log2-domain score
        p = (k >= klo && k <= khi) ? p : 0.0f;    // window + seq mask
        l += p;
        const ull pp = pack2(p, p);

        #pragma unroll
        for (int i = 0; i < 8; i++) {
            const ulonglong2 vv = vr[i];
            acc2[2*i+0] = ffma2(pp, vv.x, acc2[2*i+0]);
            acc2[2*i+1] = ffma2(pp, vv.y, acc2[2*i+1]);
        }
    }

    // ---- combine the two key splits through reused smem ----
    __syncthreads();                 // all K/V reads done; tile is scratch now

    const int SCR_G = 16 * RSTRIDE + 16;          // floats per group scratch
    float* scr = smem + g * SCR_G;

    if (sp == 1) {
        float4* ap = reinterpret_cast<float4*>(scr + ql16 * RSTRIDE + half * HOFF);
        #pragma unroll
        for (int i = 0; i < 8; i++) {
            float2 a = unpack2(acc2[2*i+0]);
            float2 b = unpack2(acc2[2*i+1]);
            ap[i] = make_float4(a.x, a.y, b.x, b.y);
        }
        if (half == 0) scr[16 * RSTRIDE + ql16] = l;
    }
    __syncthreads();

    if (sp == 0) {
        const float L   = l + scr[16 * RSTRIDE + ql16];  // >0: self-key counted
        const float inv = 1.0f / L;
        const float4* ap =
            reinterpret_cast<const float4*>(scr + ql16 * RSTRIDE + half * HOFF);
        float4* o4 = reinterpret_cast<float4*>(
            O + (size_t)(q * NH + h) * HD + half * 32);
        #pragma unroll
        for (int i = 0; i < 8; i++) {
            const float4 b = ap[i];
            float2 a0 = unpack2(acc2[2*i+0]);
            float2 a1 = unpack2(acc2[2*i+1]);
            o4[i] = make_float4((a0.x + b.x) * inv,
                                (a0.y + b.y) * inv,
                                (a1.x + b.z) * inv,
                                (a1.y + b.w) * inv);
        }
    }
}

extern "C" void kernel_launch(void* const* d_in, const int* in_sizes, int n_in,
                              void* d_out, int out_size)
{
    const float* Q = (const float*)d_in[0];
    const float* K = (const float*)d_in[1];
    const float* V = (const float*)d_in[2];
    float* O = (float*)d_out;

    cudaFuncSetAttribute(swa_kernel, cudaFuncAttributeMaxDynamicSharedMemorySize,
                         SMEM_BYTES);

    dim3 grid(S_LEN / TQ, NH);
    swa_kernel<<<grid, 256, SMEM_BYTES>>>(Q, K, V, O);
}

// round 9
// speedup vs baseline: 3.2333x; 3.2333x over previous
#include <cuda_runtime.h>
#include <cuda_bf16.h>

// Sliding-window attention B=1,S=2048,H=8,D=64,win +-64, fp32 in/out.
// FlashAttention-v2-style warp-MMA kernel with split-bf16 emulated fp32:
//   x = bf16(x) + bf16(x - bf16(x));  A*B ~= Ah*Bh + Ah*Bl + Al*Bh  (~1e-6 rel)
// Block: 128 thr / 4 warps / 64 queries. K,V staged once as bf16 hi/lo in
// swizzled smem. Warp w handles queries q0+16w..+15, key rows [16w,16w+144).
// QK: mma.m16n8k16 (A=Q frags from gmem, B=K via ldmatrix non-trans).
// P:  mask + ex2.approx on accum frags (Q pre-scaled by 0.125*log2e).
// PV: accum-layout == A-layout trick; B=V via ldmatrix.trans. Normalize at end.

#define S_LEN  2048
#define NH     8
#define HD     64
#define WIN    64
#define TQ     64
#define NROWS  192
#define ROWB   128                  // bytes per bf16 row (64*2)
#define ARR    (NROWS*ROWB)         // 24576 B per array
#define SMEM_BYTES (4*ARR)          // Khi,Klo,Vhi,Vlo = 98304 B

__device__ __forceinline__ unsigned pk(float lo, float hi) {
    unsigned d;
    asm("cvt.rn.bf16x2.f32 %0, %1, %2;" : "=r"(d) : "f"(hi), "f"(lo));
    return d;
}
__device__ __forceinline__ float up_lo(unsigned v) { return __uint_as_float(v << 16); }
__device__ __forceinline__ float up_hi(unsigned v) { return __uint_as_float(v & 0xffff0000u); }
__device__ __forceinline__ float ex2(float x) {
    float y; asm("ex2.approx.f32 %0, %1;" : "=f"(y) : "f"(x)); return y;
}
__device__ __forceinline__ unsigned s2u(const void* p) {
    unsigned a;
    asm("{ .reg .u64 t; cvta.to.shared.u64 t, %1; cvt.u32.u64 %0, t; }"
        : "=r"(a) : "l"(p));
    return a;
}
__device__ __forceinline__ void ldsm4(unsigned& r0, unsigned& r1, unsigned& r2,
                                      unsigned& r3, unsigned a) {
    asm volatile("ldmatrix.sync.aligned.m8n8.x4.shared.b16 {%0,%1,%2,%3}, [%4];"
                 : "=r"(r0), "=r"(r1), "=r"(r2), "=r"(r3) : "r"(a));
}
__device__ __forceinline__ void ldsm4t(unsigned& r0, unsigned& r1, unsigned& r2,
                                       unsigned& r3, unsigned a) {
    asm volatile("ldmatrix.sync.aligned.m8n8.x4.trans.shared.b16 {%0,%1,%2,%3}, [%4];"
                 : "=r"(r0), "=r"(r1), "=r"(r2), "=r"(r3) : "r"(a));
}
__device__ __forceinline__ void mma16816(float c[4], const unsigned a[4],
                                         unsigned b0, unsigned b1) {
    asm volatile(
        "mma.sync.aligned.m16n8k16.row.col.f32.bf16.bf16.f32 "
        "{%0,%1,%2,%3}, {%4,%5,%6,%7}, {%8,%9}, {%0,%1,%2,%3};"
        : "+f"(c[0]), "+f"(c[1]), "+f"(c[2]), "+f"(c[3])
        : "r"(a[0]), "r"(a[1]), "r"(a[2]), "r"(a[3]), "r"(b0), "r"(b1));
}

__global__ void __launch_bounds__(128, 2) swa_mma(
    const float* __restrict__ Q,
    const float* __restrict__ K,
    const float* __restrict__ V,
    float* __restrict__ O)
{
    extern __shared__ char smem[];
    const unsigned sb = s2u(smem);

    const int h    = blockIdx.y;
    const int q0   = blockIdx.x * TQ;
    const int tid  = threadIdx.x;
    const int lane = tid & 31;
    const int w    = tid >> 5;
    const int base = q0 - WIN;          // global key of smem row 0

    // ---- stage K,V as split-bf16 into swizzled smem ----
    for (int idx = tid; idx < NROWS * 16; idx += 128) {
        const int row = idx >> 4;
        const int c   = idx & 15;            // float4 chunk (16B of fp32 = 8B bf16)
        const int k   = base + row;
        float4 kf = make_float4(0.f,0.f,0.f,0.f);
        float4 vf = make_float4(0.f,0.f,0.f,0.f);
        if ((unsigned)k < S_LEN) {
            const int off = (k * NH + h) * 16 + c;
            kf = reinterpret_cast<const float4*>(K)[off];
            vf = reinterpret_cast<const float4*>(V)[off];
        }
        const unsigned so = row * ROWB + ((((c >> 1) ^ (row & 7)) << 4)) + ((c & 1) << 3);
        unsigned kh0 = pk(kf.x, kf.y), kh1 = pk(kf.z, kf.w);
        unsigned kl0 = pk(kf.x - up_lo(kh0), kf.y - up_hi(kh0));
        unsigned kl1 = pk(kf.z - up_lo(kh1), kf.w - up_hi(kh1));
        unsigned vh0 = pk(vf.x, vf.y), vh1 = pk(vf.z, vf.w);
        unsigned vl0 = pk(vf.x - up_lo(vh0), vf.y - up_hi(vh0));
        unsigned vl1 = pk(vf.z - up_lo(vh1), vf.w - up_hi(vh1));
        *reinterpret_cast<uint2*>(smem + so)            = make_uint2(kh0, kh1);
        *reinterpret_cast<uint2*>(smem + ARR + so)      = make_uint2(kl0, kl1);
        *reinterpret_cast<uint2*>(smem + 2*ARR + so)    = make_uint2(vh0, vh1);
        *reinterpret_cast<uint2*>(smem + 3*ARR + so)    = make_uint2(vl0, vl1);
    }

    // ---- per-thread Q fragments (m16k16), scaled by 0.125*log2(e), split ----
    const int qw   = q0 + 16 * w;
    const int r    = lane >> 2;
    const int col0 = (lane & 3) * 2;
    const float sc = 0.125f * 1.44269504088896340736f;

    unsigned qh[4][4], ql[4][4];
    {
        const float* Q0 = Q + (size_t)((qw + r)     * NH + h) * HD;
        const float* Q8 = Q + (size_t)((qw + r + 8) * NH + h) * HD;
        #pragma unroll
        for (int kt = 0; kt < 4; kt++) {
            float2 e0 = *reinterpret_cast<const float2*>(Q0 + kt*16 + col0);
            float2 e1 = *reinterpret_cast<const float2*>(Q8 + kt*16 + col0);
            float2 e2 = *reinterpret_cast<const float2*>(Q0 + kt*16 + col0 + 8);
            float2 e3 = *reinterpret_cast<const float2*>(Q8 + kt*16 + col0 + 8);
            e0.x*=sc; e0.y*=sc; e1.x*=sc; e1.y*=sc;
            e2.x*=sc; e2.y*=sc; e3.x*=sc; e3.y*=sc;
            qh[kt][0]=pk(e0.x,e0.y); qh[kt][1]=pk(e1.x,e1.y);
            qh[kt][2]=pk(e2.x,e2.y); qh[kt][3]=pk(e3.x,e3.y);
            ql[kt][0]=pk(e0.x-up_lo(qh[kt][0]), e0.y-up_hi(qh[kt][0]));
            ql[kt][1]=pk(e1.x-up_lo(qh[kt][1]), e1.y-up_hi(qh[kt][1]));
            ql[kt][2]=pk(e2.x-up_lo(qh[kt][2]), e2.y-up_hi(qh[kt][2]));
            ql[kt][3]=pk(e3.x-up_lo(qh[kt][3]), e3.y-up_hi(qh[kt][3]));
        }
    }

    __syncthreads();

    // ---- main loop over 9 key-steps of 16 keys ----
    float o[8][4];
    #pragma unroll
    for (int n = 0; n < 8; n++)
        #pragma unroll
        for (int j = 0; j < 4; j++) o[n][j] = 0.f;
    float lr = 0.f, lr8 = 0.f;

    const int gq   = lane >> 3;        // ldmatrix address group
    const int iq   = lane & 7;
    const int wrow = 16 * w;
    const int rA0  = wrow + ((gq >> 1) << 3) + iq;   // QK addr row (pre ks)
    const int rB0  = wrow + ((gq & 1) << 3) + iq;    // PV addr row (pre ks)
    const int kbw  = base + wrow;                    // global key of warp row 0

    #pragma unroll 1
    for (int ks = 0; ks < 9; ks++) {
        // ---- QK: two n-tiles (keys ks*16..+7, +8..+15) ----
        float c0[4] = {0,0,0,0}, c1[4] = {0,0,0,0};
        const int rowA = rA0 + ks * 16;
        const unsigned aAbase = sb + rowA * ROWB;
        #pragma unroll
        for (int kt = 0; kt < 4; kt++) {
            const unsigned aK = aAbase + ((((2*kt) + (gq & 1)) ^ (rowA & 7)) << 4);
            unsigned b0,b1,b2,b3, l0,l1,l2,l3;
            ldsm4(b0,b1,b2,b3, aK);          // K hi
            ldsm4(l0,l1,l2,l3, aK + ARR);    // K lo
            mma16816(c0, qh[kt], b0, b1);  mma16816(c1, qh[kt], b2, b3);
            mma16816(c0, qh[kt], l0, l1);  mma16816(c1, qh[kt], l2, l3);
            mma16816(c0, ql[kt], b0, b1);  mma16816(c1, ql[kt], b2, b3);
        }

        // ---- mask + exp2 (scores already in log2 domain) ----
        const int nta  = 2 * ks;
        const int d00  = nta*8 + col0 - 64 - r;   // key - query for c=0,h=0
        const int keyb = kbw + nta*8 + col0;
        #pragma unroll
        for (int t2 = 0; t2 < 2; t2++) {
            float* cc = t2 ? c1 : c0;
            const int dd = d00 + 8*t2;
            const int kk = keyb + 8*t2;
            float p0 = ((unsigned)(dd + 64)     <= 128 && (unsigned)kk     < S_LEN) ? ex2(cc[0]) : 0.f;
            float p1 = ((unsigned)(dd + 65)     <= 128 && (unsigned)(kk+1) < S_LEN) ? ex2(cc[1]) : 0.f;
            float p2 = ((unsigned)(dd + 56)     <= 128 && (unsigned)kk     < S_LEN) ? ex2(cc[2]) : 0.f;
            float p3 = ((unsigned)(dd + 57)     <= 128 && (unsigned)(kk+1) < S_LEN) ? ex2(cc[3]) : 0.f;
            cc[0]=p0; cc[1]=p1; cc[2]=p2; cc[3]=p3;
            lr  += p0 + p1;
            lr8 += p2 + p3;
        }

        // ---- P fragments (accum layout == A layout), split-bf16 ----
        unsigned ph[4], pl[4];
        ph[0] = pk(c0[0], c0[1]); ph[1] = pk(c0[2], c0[3]);
        ph[2] = pk(c1[0], c1[1]); ph[3] = pk(c1[2], c1[3]);
        pl[0] = pk(c0[0]-up_lo(ph[0]), c0[1]-up_hi(ph[0]));
        pl[1] = pk(c0[2]-up_lo(ph[1]), c0[3]-up_hi(ph[1]));
        pl[2] = pk(c1[0]-up_lo(ph[2]), c1[1]-up_hi(ph[2]));
        pl[3] = pk(c1[2]-up_lo(ph[3]), c1[3]-up_hi(ph[3]));

        // ---- PV: 8 n-tiles of dims ----
        const int rowB = rB0 + ks * 16;
        const unsigned aBbase = sb + 2*ARR + rowB * ROWB;
        #pragma unroll
        for (int dq = 0; dq < 4; dq++) {
            const unsigned aV = aBbase + ((((2*dq) + (gq >> 1)) ^ (rowB & 7)) << 4);
            unsigned v0,v1,v2,v3, u0,u1,u2,u3;
            ldsm4t(v0,v1,v2,v3, aV);         // V hi
            ldsm4t(u0,u1,u2,u3, aV + ARR);   // V lo
            mma16816(o[2*dq],   ph, v0, v1);  mma16816(o[2*dq+1], ph, v2, v3);
            mma16816(o[2*dq],   ph, u0, u1);  mma16816(o[2*dq+1], ph, u2, u3);
            mma16816(o[2*dq],   pl, v0, v1);  mma16816(o[2*dq+1], pl, v2, v3);
        }
    }

    // ---- normalize + store ----
    lr  += __shfl_xor_sync(0xffffffffu, lr, 1);
    lr  += __shfl_xor_sync(0xffffffffu, lr, 2);
    lr8 += __shfl_xor_sync(0xffffffffu, lr8, 1);
    lr8 += __shfl_xor_sync(0xffffffffu, lr8, 2);
    const float inv  = 1.0f / lr;
    const float inv8 = 1.0f / lr8;

    float* O0 = O + (size_t)((qw + r)     * NH + h) * HD;
    float* O8 = O + (size_t)((qw + r + 8) * NH + h) * HD;
    #pragma unroll
    for (int n = 0; n < 8; n++) {
        *reinterpret_cast<float2*>(O0 + n*8 + col0) =
            make_float2(o[n][0] * inv,  o[n][1] * inv);
        *reinterpret_cast<float2*>(O8 + n*8 + col0) =
            make_float2(o[n][2] * inv8, o[n][3] * inv8);
    }
}

extern "C" void kernel_launch(void* const* d_in, const int* in_sizes, int n_in,
                              void* d_out, int out_size)
{
    const float* Q = (const float*)d_in[0];
    const float* K = (const float*)d_in[1];
    const float* V = (const float*)d_in[2];
    float* O = (float*)d_out;

    cudaFuncSetAttribute(swa_mma, cudaFuncAttributeMaxDynamicSharedMemorySize,
                         SMEM_BYTES);

    dim3 grid(S_LEN / TQ, NH);
    swa_mma<<<grid, 128, SMEM_BYTES>>>(Q, K, V, O);
}